// round 2
// baseline (speedup 1.0000x reference)
#include <cuda_runtime.h>
#include <cuda_bf16.h>
#include <math.h>

// ---------------- problem constants ----------------
#define BATCH 32
#define TSEQ  1024
#define MEL   40
#define CD    128
#define HID   256
#define NCLS  10
#define NCTA  128   // persistent GRU grid

// ---------------- device scratch (no mallocs allowed) ----------------
__device__ float g_f1[(size_t)BATCH*CD*TSEQ*8];    // conv1 output (pooled to 8)
__device__ float g_f2[(size_t)BATCH*CD*TSEQ*2];    // conv2 output (pooled to 2)
__device__ float g_feats[(size_t)TSEQ*BATCH*CD];   // conv3 output [t][b][cd]
__device__ float g_gi[(size_t)TSEQ*768*BATCH];     // precomputed gi feature part [t][j][b]
__device__ float g_h[2][BATCH*HID];                // h ping-pong
__device__ float g_tf[2][BATCH*NCLS];              // teacher-force ping-pong
__device__ unsigned g_bar;                         // grid barrier counter (reset each run)

// ============================================================
// conv1: [B,1,T,40] -> 3x3 same conv (1->128) + relu + pool(1,5) -> g_f1 [B,128,T,8]
// ============================================================
__global__ __launch_bounds__(512) void conv1_kernel(
    const float* __restrict__ x, const float* __restrict__ W1,
    const float* __restrict__ b1)
{
    __shared__ float x_s[6][42];
    const int tid = threadIdx.x;
    const int tl  = tid & 3;       // 0..3 (t within block)
    const int co  = tid >> 2;      // 0..127
    const int t0  = blockIdx.x * 4;
    const int b   = blockIdx.y;

    for (int e = tid; e < 6*42; e += 512) {
        int r = e / 42, c = e - r*42;
        int gt = t0 + r - 1, gm = c - 1;
        float v = 0.f;
        if (gt >= 0 && gt < TSEQ && gm >= 0 && gm < MEL)
            v = x[((size_t)b*TSEQ + gt)*MEL + gm];
        x_s[r][c] = v;
    }
    __syncthreads();

    float w[9];
#pragma unroll
    for (int k = 0; k < 9; k++) w[k] = __ldg(W1 + co*9 + k);
    const float bv = __ldg(b1 + co);
    const int t = t0 + tl;

    float a0 = x_s[tl+0][0], a1 = x_s[tl+1][0], a2 = x_s[tl+2][0];
    float c0 = x_s[tl+0][1], c1 = x_s[tl+1][1], c2 = x_s[tl+2][1];
    float mx = 0.f; int mp = 0, cnt = 0;
#pragma unroll
    for (int m = 0; m < MEL; m++) {
        float d0 = x_s[tl+0][m+2], d1 = x_s[tl+1][m+2], d2 = x_s[tl+2][m+2];
        float s = bv;
        s = fmaf(w[0], a0, s); s = fmaf(w[1], c0, s); s = fmaf(w[2], d0, s);
        s = fmaf(w[3], a1, s); s = fmaf(w[4], c1, s); s = fmaf(w[5], d1, s);
        s = fmaf(w[6], a2, s); s = fmaf(w[7], c2, s); s = fmaf(w[8], d2, s);
        s = fmaxf(s, 0.f);
        mx = fmaxf(mx, s);
        a0 = c0; a1 = c1; a2 = c2; c0 = d0; c1 = d1; c2 = d2;
        if (++cnt == 5) {
            g_f1[(((size_t)b*CD + co)*TSEQ + t)*8 + mp] = mx;
            mx = 0.f; cnt = 0; mp++;
        }
    }
}

// ============================================================
// conv_cc: 128->128 channel 3x3 same conv + relu + pool(1,POOL)
// MIN = input mel width (8 or 2). TOFEATS: write g_feats[t][b][co].
// grid: (4 co-blocks, T/8, B), block 256 = 32 co x 8 t
// ============================================================
template<int MIN, int POOL, bool TOFEATS>
__global__ __launch_bounds__(256) void conv_cc_kernel(
    const float* __restrict__ in, const float* __restrict__ W,
    const float* __restrict__ bias, float* __restrict__ outp)
{
    constexpr int MPAD = MIN + 2;
    __shared__ float w_s[32][8][9];
    __shared__ float in_s[8][10][MPAD];

    const int tid = threadIdx.x;
    const int tl  = tid & 7;        // t within block
    const int col = tid >> 3;       // co within block (0..31)
    const int co  = blockIdx.x*32 + col;
    const int t0  = blockIdx.y*8;
    const int b   = blockIdx.z;
    const int t   = t0 + tl;

    float acc[MIN];
#pragma unroll
    for (int m = 0; m < MIN; m++) acc[m] = 0.f;

    for (int cc = 0; cc < 16; cc++) {
        const int ci0 = cc*8;
        for (int e = tid; e < 2304; e += 256) {
            int lc = e/72; int rem = e - lc*72; int cl = rem/9; int k = rem - cl*9;
            w_s[lc][cl][k] = W[((size_t)(blockIdx.x*32 + lc)*CD + ci0 + cl)*9 + k];
        }
        constexpr int NIN = 8*10*MPAD;
        for (int e = tid; e < NIN; e += 256) {
            int cl = e/(10*MPAD); int rem = e - cl*(10*MPAD);
            int r = rem/MPAD; int c = rem - r*MPAD;
            int gt = t0 + r - 1, gm = c - 1;
            float v = 0.f;
            if (gt >= 0 && gt < TSEQ && gm >= 0 && gm < MIN)
                v = in[((size_t)(b*CD + ci0 + cl)*TSEQ + gt)*MIN + gm];
            in_s[cl][r][c] = v;
        }
        __syncthreads();
#pragma unroll
        for (int cl = 0; cl < 8; cl++) {
            float w00=w_s[col][cl][0], w01=w_s[col][cl][1], w02=w_s[col][cl][2];
            float w10=w_s[col][cl][3], w11=w_s[col][cl][4], w12=w_s[col][cl][5];
            float w20=w_s[col][cl][6], w21=w_s[col][cl][7], w22=w_s[col][cl][8];
            float a0=in_s[cl][tl+0][0], a1=in_s[cl][tl+1][0], a2=in_s[cl][tl+2][0];
            float c0=in_s[cl][tl+0][1], c1=in_s[cl][tl+1][1], c2=in_s[cl][tl+2][1];
#pragma unroll
            for (int m = 0; m < MIN; m++) {
                float d0=in_s[cl][tl+0][m+2], d1=in_s[cl][tl+1][m+2], d2=in_s[cl][tl+2][m+2];
                float s = acc[m];
                s = fmaf(w00, a0, s); s = fmaf(w01, c0, s); s = fmaf(w02, d0, s);
                s = fmaf(w10, a1, s); s = fmaf(w11, c1, s); s = fmaf(w12, d1, s);
                s = fmaf(w20, a2, s); s = fmaf(w21, c2, s); s = fmaf(w22, d2, s);
                acc[m] = s;
                a0=c0; a1=c1; a2=c2; c0=d0; c1=d1; c2=d2;
            }
        }
        __syncthreads();
    }

    const float bv = __ldg(bias + co);
    if (TOFEATS) {
        float y0 = fmaxf(acc[0] + bv, 0.f);
        float y1 = fmaxf(acc[1] + bv, 0.f);
        outp[((size_t)t*BATCH + b)*CD + co] = fmaxf(y0, y1);
    } else {
        constexpr int MOUT = MIN / POOL;
#pragma unroll
        for (int mp = 0; mp < MOUT; mp++) {
            float mx = 0.f;
#pragma unroll
            for (int q = 0; q < POOL; q++)
                mx = fmaxf(mx, fmaxf(acc[mp*POOL + q] + bv, 0.f));
            outp[(((size_t)b*CD + co)*TSEQ + t)*MOUT + mp] = mx;
        }
    }
}

// ============================================================
// gi GEMM: g_gi[t][j][b] = b_ih[j] + sum_k feats[t][b][k] * W_ih[j][k]  (k<128)
// A = g_feats [32768 x 128] row-major, B = W_ih [768 x 138] (first 128 cols)
// grid (12, 512), block 256, 4x4 register tile, 64x64 CTA tile, k-chunks of 32
// ============================================================
__global__ __launch_bounds__(256) void gi_gemm_kernel(
    const float* __restrict__ Wih, const float* __restrict__ bih)
{
    __shared__ float As[64][33];
    __shared__ float Bs[64][33];
    const int tid = threadIdx.x;
    const int j0 = blockIdx.x * 64;
    const int r0 = blockIdx.y * 64;
    const int ty = tid >> 4, tx = tid & 15;
    float acc[4][4] = {};

    for (int kc = 0; kc < 4; kc++) {
        const int k0 = kc * 32;
        for (int e = tid; e < 64*32; e += 256) {
            int rr = e >> 5, k = e & 31;
            As[rr][k] = g_feats[(size_t)(r0 + rr)*CD + k0 + k];
            Bs[rr][k] = Wih[(size_t)(j0 + rr)*138 + k0 + k];
        }
        __syncthreads();
#pragma unroll
        for (int k = 0; k < 32; k++) {
            float a[4], bb[4];
#pragma unroll
            for (int i = 0; i < 4; i++) { a[i] = As[ty*4+i][k]; bb[i] = Bs[tx*4+i][k]; }
#pragma unroll
            for (int i = 0; i < 4; i++)
#pragma unroll
                for (int jj = 0; jj < 4; jj++)
                    acc[i][jj] = fmaf(a[i], bb[jj], acc[i][jj]);
        }
        __syncthreads();
    }
#pragma unroll
    for (int i = 0; i < 4; i++) {
        int r = r0 + ty*4 + i; int t = r >> 5; int b = r & 31;
#pragma unroll
        for (int jj = 0; jj < 4; jj++) {
            int j = j0 + tx*4 + jj;
            g_gi[((size_t)t*768 + j)*BATCH + b] = acc[i][jj] + __ldg(bih + j);
        }
    }
}

// ============================================================
// persistent GRU: 128 CTAs x 192 threads, grid barriers, 1024 steps.
// CTA c owns hidden units m = {2c, 2c+1}; thread = (gate g, mloc, b).
// ============================================================
__device__ __forceinline__ void grid_barrier(unsigned target)
{
    __syncthreads();
    if (threadIdx.x == 0) {
        __threadfence();
        atomicAdd(&g_bar, 1u);
        while (*((volatile unsigned*)&g_bar) < target) { }
    }
    __syncthreads();
}

__global__ __launch_bounds__(192) void gru_kernel(
    const float* __restrict__ targets, const int* __restrict__ fmask,
    const float* __restrict__ Wih, const float* __restrict__ Whh,
    const float* __restrict__ bhh, const float* __restrict__ Wf,
    const float* __restrict__ bfv, float* __restrict__ outp)
{
    __shared__ float h_s[32][260];       // padded, float4-friendly
    __shared__ float tf_s[BATCH*NCLS];
    __shared__ float pre_i[3][64];
    __shared__ float pre_h[3][64];

    const int tid  = threadIdx.x;
    const int b    = tid & 31;
    const int mloc = (tid >> 5) & 1;
    const int g    = tid / 64;                 // 0=r,1=z,2=n
    const int m    = blockIdx.x*2 + mloc;
    const int j    = g*HID + m;
    unsigned barno = 0;

    // zero-init h0, tf0
    {
        int gt = blockIdx.x*192 + tid;
        for (int e = gt; e < BATCH*HID; e += NCTA*192) g_h[0][e] = 0.f;
        for (int e = gt; e < BATCH*NCLS; e += NCTA*192) g_tf[0][e] = 0.f;
    }
    grid_barrier(++barno * NCTA);

    const float4* wrow = reinterpret_cast<const float4*>(Whh + (size_t)j*HID);
    const float bhv = __ldg(bhh + j);

    for (int t = 0; t < TSEQ; t++) {
        const int p = t & 1, pn = p ^ 1;

        // stage h(t-1), tf(t-1) into smem (L1-bypassing loads)
        {
            const float4* hp = reinterpret_cast<const float4*>(g_h[p]);
            for (int e = tid; e < BATCH*HID/4; e += 192) {
                float4 v = __ldcg(hp + e);
                int bb = e >> 6, k4 = e & 63;
                *reinterpret_cast<float4*>(&h_s[bb][k4*4]) = v;
            }
            for (int e = tid; e < BATCH*NCLS; e += 192)
                tf_s[e] = __ldcg(&g_tf[p][e]);
        }
        __syncthreads();

        // phase 1: gate pre-activations
        float gi = __ldg(&g_gi[((size_t)t*768 + j)*BATCH + b]);
#pragma unroll
        for (int c = 0; c < NCLS; c++)
            gi = fmaf(tf_s[b*NCLS + c], __ldg(Wih + (size_t)j*138 + CD + c), gi);

        float gh = bhv;
#pragma unroll 8
        for (int k4 = 0; k4 < HID/4; k4++) {
            float4 w  = __ldg(wrow + k4);
            float4 hv = *reinterpret_cast<const float4*>(&h_s[b][k4*4]);
            gh = fmaf(w.x, hv.x, gh); gh = fmaf(w.y, hv.y, gh);
            gh = fmaf(w.z, hv.z, gh); gh = fmaf(w.w, hv.w, gh);
        }
        pre_i[g][mloc*32 + b] = gi;
        pre_h[g][mloc*32 + b] = gh;
        __syncthreads();

        // phase 1b: h update for this CTA's 2 hidden units
        if (tid < 64) {
            int bb = tid & 31, ml = tid >> 5;
            float r = 1.f/(1.f + expf(-(pre_i[0][tid] + pre_h[0][tid])));
            float z = 1.f/(1.f + expf(-(pre_i[1][tid] + pre_h[1][tid])));
            float n = tanhf(pre_i[2][tid] + r*pre_h[2][tid]);
            int mm = blockIdx.x*2 + ml;
            float hold = h_s[bb][mm];
            float hnew = (1.f - z)*n + z*hold;
            g_h[pn][bb*HID + mm] = hnew;
        }
        grid_barrier(++barno * NCTA);   // publish h(t)

        // phase 2: output head + teacher-force update (CTAs 0..31 = one b each)
        if (blockIdx.x < 32 && tid < NCLS) {
            int bb = blockIdx.x, c = tid;
            const float4* hv = reinterpret_cast<const float4*>(g_h[pn] + bb*HID);
            const float4* wv = reinterpret_cast<const float4*>(Wf + c*HID);
            float acc = __ldg(bfv + c);
#pragma unroll 8
            for (int k4 = 0; k4 < HID/4; k4++) {
                float4 h4 = __ldcg(hv + k4);
                float4 w4 = __ldg(wv + k4);
                acc = fmaf(h4.x, w4.x, acc); acc = fmaf(h4.y, w4.y, acc);
                acc = fmaf(h4.z, w4.z, acc); acc = fmaf(h4.w, w4.w, acc);
            }
            outp[((size_t)bb*TSEQ + t)*NCLS + c] = acc;
            int fm = __ldg(fmask + t*BATCH + bb);
            float tg = __ldg(targets + ((size_t)bb*TSEQ + t)*NCLS + c);
            g_tf[pn][bb*NCLS + c] = (fm > 0) ? tg : (acc > 0.f ? 1.f : 0.f);
        }
        grid_barrier(++barno * NCTA);   // publish tf(t)
    }
}

__global__ void bar_reset_kernel() { g_bar = 0u; }

// ============================================================
// launch
// ============================================================
extern "C" void kernel_launch(void* const* d_in, const int* in_sizes, int n_in,
                              void* d_out, int out_size)
{
    const float* x       = (const float*)d_in[0];
    const float* targets = (const float*)d_in[1];
    const int*   fmask   = (const int*)  d_in[2];
    const float* W1      = (const float*)d_in[3];
    const float* b1      = (const float*)d_in[4];
    const float* W2      = (const float*)d_in[5];
    const float* b2      = (const float*)d_in[6];
    const float* W3      = (const float*)d_in[7];
    const float* b3      = (const float*)d_in[8];
    const float* W_ih    = (const float*)d_in[9];
    const float* W_hh    = (const float*)d_in[10];
    const float* b_ih    = (const float*)d_in[11];
    const float* b_hh    = (const float*)d_in[12];
    const float* Wf      = (const float*)d_in[13];
    const float* bf      = (const float*)d_in[14];
    float* outp = (float*)d_out;

    float *f1p, *f2p, *featsp;
    cudaGetSymbolAddress((void**)&f1p,    g_f1);
    cudaGetSymbolAddress((void**)&f2p,    g_f2);
    cudaGetSymbolAddress((void**)&featsp, g_feats);

    conv1_kernel<<<dim3(TSEQ/4, BATCH), 512>>>(x, W1, b1);
    conv_cc_kernel<8, 4, false><<<dim3(4, TSEQ/8, BATCH), 256>>>(f1p, W2, b2, f2p);
    conv_cc_kernel<2, 2, true ><<<dim3(4, TSEQ/8, BATCH), 256>>>(f2p, W3, b3, featsp);
    gi_gemm_kernel<<<dim3(12, 512), 256>>>(W_ih, b_ih);
    gru_kernel<<<NCTA, 192>>>(targets, fmask, W_ih, W_hh, b_hh, Wf, bf, outp);
    bar_reset_kernel<<<1, 1>>>();
}

// round 3
// speedup vs baseline: 3.2711x; 3.2711x over previous
#include <cuda_runtime.h>
#include <cuda_bf16.h>
#include <math.h>

// ---------------- problem constants ----------------
#define BATCH 32
#define TSEQ  1024
#define MEL   40
#define CD    128
#define HID   256
#define NCLS  10

// ---------------- device scratch ----------------
__device__ float g_f1[(size_t)BATCH*CD*TSEQ*8];    // conv1 output (pooled to 8)
__device__ float g_f2[(size_t)BATCH*CD*TSEQ*2];    // conv2 output (pooled to 2)
__device__ float g_feats[(size_t)TSEQ*BATCH*CD];   // conv3 output [t][b][cd]
__device__ float g_gi[(size_t)TSEQ*BATCH*768];     // precomputed gi (feature part + b_ih) [t*32+b][j]

// ---------------- asm helpers ----------------
__device__ __forceinline__ unsigned long long fma2(unsigned long long a,
                                                   unsigned long long b,
                                                   unsigned long long c) {
    unsigned long long d;
    asm("fma.rn.f32x2 %0, %1, %2, %3;" : "=l"(d) : "l"(a), "l"(b), "l"(c));
    return d;
}
__device__ __forceinline__ float2 ull2f2(unsigned long long v) {
    float2 f;
    asm("mov.b64 {%0, %1}, %2;" : "=f"(f.x), "=f"(f.y) : "l"(v));
    return f;
}
__device__ __forceinline__ unsigned smem_u32(const void* p) {
    unsigned r;
    asm("{ .reg .u64 t; cvta.to.shared.u64 t, %1; cvt.u32.u64 %0, t; }"
        : "=r"(r) : "l"(p));
    return r;
}
__device__ __forceinline__ unsigned mapa_rank(unsigned addr, unsigned rank) {
    unsigned r;
    asm("mapa.shared::cluster.u32 %0, %1, %2;" : "=r"(r) : "r"(addr), "r"(rank));
    return r;
}
__device__ __forceinline__ void st_cluster_f32(unsigned addr, float v) {
    asm volatile("st.shared::cluster.f32 [%0], %1;" :: "r"(addr), "f"(v) : "memory");
}

// ============================================================
// conv1: [B,1,T,40] -> 3x3 same conv (1->128) + relu + pool(1,5) -> g_f1 [B,128,T,8]
// ============================================================
__global__ __launch_bounds__(512) void conv1_kernel(
    const float* __restrict__ x, const float* __restrict__ W1,
    const float* __restrict__ b1)
{
    __shared__ float x_s[6][42];
    const int tid = threadIdx.x;
    const int tl  = tid & 3;
    const int co  = tid >> 2;
    const int t0  = blockIdx.x * 4;
    const int b   = blockIdx.y;

    for (int e = tid; e < 6*42; e += 512) {
        int r = e / 42, c = e - r*42;
        int gt = t0 + r - 1, gm = c - 1;
        float v = 0.f;
        if (gt >= 0 && gt < TSEQ && gm >= 0 && gm < MEL)
            v = x[((size_t)b*TSEQ + gt)*MEL + gm];
        x_s[r][c] = v;
    }
    __syncthreads();

    float w[9];
#pragma unroll
    for (int k = 0; k < 9; k++) w[k] = __ldg(W1 + co*9 + k);
    const float bv = __ldg(b1 + co);
    const int t = t0 + tl;

    float a0 = x_s[tl+0][0], a1 = x_s[tl+1][0], a2 = x_s[tl+2][0];
    float c0 = x_s[tl+0][1], c1 = x_s[tl+1][1], c2 = x_s[tl+2][1];
    float mx = 0.f; int mp = 0, cnt = 0;
#pragma unroll
    for (int m = 0; m < MEL; m++) {
        float d0 = x_s[tl+0][m+2], d1 = x_s[tl+1][m+2], d2 = x_s[tl+2][m+2];
        float s = bv;
        s = fmaf(w[0], a0, s); s = fmaf(w[1], c0, s); s = fmaf(w[2], d0, s);
        s = fmaf(w[3], a1, s); s = fmaf(w[4], c1, s); s = fmaf(w[5], d1, s);
        s = fmaf(w[6], a2, s); s = fmaf(w[7], c2, s); s = fmaf(w[8], d2, s);
        s = fmaxf(s, 0.f);
        mx = fmaxf(mx, s);
        a0 = c0; a1 = c1; a2 = c2; c0 = d0; c1 = d1; c2 = d2;
        if (++cnt == 5) {
            g_f1[(((size_t)b*CD + co)*TSEQ + t)*8 + mp] = mx;
            mx = 0.f; cnt = 0; mp++;
        }
    }
}

// ============================================================
// conv_cc: 128->128 channel 3x3 same conv + relu + pool(1,POOL)
// ============================================================
template<int MIN, int POOL, bool TOFEATS>
__global__ __launch_bounds__(256) void conv_cc_kernel(
    const float* __restrict__ in, const float* __restrict__ W,
    const float* __restrict__ bias, float* __restrict__ outp)
{
    constexpr int MPAD = MIN + 2;
    __shared__ float w_s[32][8][9];
    __shared__ float in_s[8][10][MPAD];

    const int tid = threadIdx.x;
    const int tl  = tid & 7;
    const int col = tid >> 3;
    const int co  = blockIdx.x*32 + col;
    const int t0  = blockIdx.y*8;
    const int b   = blockIdx.z;
    const int t   = t0 + tl;

    float acc[MIN];
#pragma unroll
    for (int m = 0; m < MIN; m++) acc[m] = 0.f;

    for (int cc = 0; cc < 16; cc++) {
        const int ci0 = cc*8;
        for (int e = tid; e < 2304; e += 256) {
            int lc = e/72; int rem = e - lc*72; int cl = rem/9; int k = rem - cl*9;
            w_s[lc][cl][k] = W[((size_t)(blockIdx.x*32 + lc)*CD + ci0 + cl)*9 + k];
        }
        constexpr int NIN = 8*10*MPAD;
        for (int e = tid; e < NIN; e += 256) {
            int cl = e/(10*MPAD); int rem = e - cl*(10*MPAD);
            int r = rem/MPAD; int c = rem - r*MPAD;
            int gt = t0 + r - 1, gm = c - 1;
            float v = 0.f;
            if (gt >= 0 && gt < TSEQ && gm >= 0 && gm < MIN)
                v = in[((size_t)(b*CD + ci0 + cl)*TSEQ + gt)*MIN + gm];
            in_s[cl][r][c] = v;
        }
        __syncthreads();
#pragma unroll
        for (int cl = 0; cl < 8; cl++) {
            float w00=w_s[col][cl][0], w01=w_s[col][cl][1], w02=w_s[col][cl][2];
            float w10=w_s[col][cl][3], w11=w_s[col][cl][4], w12=w_s[col][cl][5];
            float w20=w_s[col][cl][6], w21=w_s[col][cl][7], w22=w_s[col][cl][8];
            float a0=in_s[cl][tl+0][0], a1=in_s[cl][tl+1][0], a2=in_s[cl][tl+2][0];
            float c0=in_s[cl][tl+0][1], c1=in_s[cl][tl+1][1], c2=in_s[cl][tl+2][1];
#pragma unroll
            for (int m = 0; m < MIN; m++) {
                float d0=in_s[cl][tl+0][m+2], d1=in_s[cl][tl+1][m+2], d2=in_s[cl][tl+2][m+2];
                float s = acc[m];
                s = fmaf(w00, a0, s); s = fmaf(w01, c0, s); s = fmaf(w02, d0, s);
                s = fmaf(w10, a1, s); s = fmaf(w11, c1, s); s = fmaf(w12, d1, s);
                s = fmaf(w20, a2, s); s = fmaf(w21, c2, s); s = fmaf(w22, d2, s);
                acc[m] = s;
                a0=c0; a1=c1; a2=c2; c0=d0; c1=d1; c2=d2;
            }
        }
        __syncthreads();
    }

    const float bv = __ldg(bias + co);
    if (TOFEATS) {
        float y0 = fmaxf(acc[0] + bv, 0.f);
        float y1 = fmaxf(acc[1] + bv, 0.f);
        outp[((size_t)t*BATCH + b)*CD + co] = fmaxf(y0, y1);
    } else {
        constexpr int MOUT = MIN / POOL;
#pragma unroll
        for (int mp = 0; mp < MOUT; mp++) {
            float mx = 0.f;
#pragma unroll
            for (int q = 0; q < POOL; q++)
                mx = fmaxf(mx, fmaxf(acc[mp*POOL + q] + bv, 0.f));
            outp[(((size_t)b*CD + co)*TSEQ + t)*MOUT + mp] = mx;
        }
    }
}

// ============================================================
// gi GEMM: g_gi[r][j] = b_ih[j] + sum_k feats[r][k] * W_ih[j][k]  (k<128, r=t*32+b)
// ============================================================
__global__ __launch_bounds__(256) void gi_gemm_kernel(
    const float* __restrict__ Wih, const float* __restrict__ bih)
{
    __shared__ float As[64][33];
    __shared__ float Bs[64][33];
    const int tid = threadIdx.x;
    const int j0 = blockIdx.x * 64;
    const int r0 = blockIdx.y * 64;
    const int ty = tid >> 4, tx = tid & 15;
    float acc[4][4] = {};

    for (int kc = 0; kc < 4; kc++) {
        const int k0 = kc * 32;
        for (int e = tid; e < 64*32; e += 256) {
            int rr = e >> 5, k = e & 31;
            As[rr][k] = g_feats[(size_t)(r0 + rr)*CD + k0 + k];
            Bs[rr][k] = Wih[(size_t)(j0 + rr)*138 + k0 + k];
        }
        __syncthreads();
#pragma unroll
        for (int k = 0; k < 32; k++) {
            float a[4], bb[4];
#pragma unroll
            for (int i = 0; i < 4; i++) { a[i] = As[ty*4+i][k]; bb[i] = Bs[tx*4+i][k]; }
#pragma unroll
            for (int i = 0; i < 4; i++)
#pragma unroll
                for (int jj = 0; jj < 4; jj++)
                    acc[i][jj] = fmaf(a[i], bb[jj], acc[i][jj]);
        }
        __syncthreads();
    }
#pragma unroll
    for (int i = 0; i < 4; i++) {
        int r = r0 + ty*4 + i;
#pragma unroll
        for (int jj = 0; jj < 4; jj++) {
            int j = j0 + tx*4 + jj;
            g_gi[(size_t)r*768 + j] = acc[i][jj] + __ldg(bih + j);
        }
    }
}

// ============================================================
// GRU: 32 clusters of 4 CTAs (one cluster per batch element).
// CTA rank r owns hidden units [r*64, r*64+64) -> 192 rows of W_hh/W_ih,
// kept entirely in registers (128 floats/thread, 384 threads).
// One DSMEM exchange + one cluster barrier per timestep.
// ============================================================
__global__ void __cluster_dims__(4, 1, 1) __launch_bounds__(384, 1)
gru_kernel(
    const float* __restrict__ targets, const int* __restrict__ fmask,
    const float* __restrict__ Wih, const float* __restrict__ Whh,
    const float* __restrict__ bhh, const float* __restrict__ Wf,
    const float* __restrict__ bfv, float* __restrict__ outp)
{
    __shared__ __align__(16) float h_s[2][HID];   // full h, double buffered
    __shared__ float part_s[192][3];              // gh partials (2 k-halves)
    __shared__ float pre_s[128];                  // r,z preactivations (gi+gh)
    __shared__ float gin_s[64], ghn_s[64];        // n-gate split
    __shared__ float op_s[2][4][NCLS];            // out partials per rank
    __shared__ float tf_s[NCLS];                  // teacher-force state
    __shared__ float wtf_s[192][11];              // W_ih tf columns

    const int tid = threadIdx.x;
    unsigned rank;
    asm("mov.u32 %0, %%cluster_ctarank;" : "=r"(rank));
    const int b = blockIdx.x >> 2;
    const int kh = (tid >= 192) ? 1 : 0;          // k-half
    const int jl = tid - kh*192;                  // j_local 0..191
    const int g  = jl >> 6, u = jl & 63;
    const int jglob = g*HID + (int)rank*64 + u;

    // --- persistent register weights: W_hh[jglob][kh*128 .. +128) ---
    unsigned long long warr[64];
    {
        const ulonglong2* wp = reinterpret_cast<const ulonglong2*>(
            Whh + (size_t)jglob*HID + kh*128);
#pragma unroll
        for (int i = 0; i < 32; i++) {
            ulonglong2 v = wp[i];
            warr[2*i] = v.x; warr[2*i+1] = v.y;
        }
    }
    const float bhv = __ldg(bhh + jglob);

    if (tid < 192) {
#pragma unroll
        for (int c = 0; c < NCLS; c++)
            wtf_s[tid][c] = __ldg(Wih + (size_t)jglob*138 + CD + c);
    }
    float wf0 = 0.f, wf1 = 0.f;
    if (tid < 320) {
        int c = tid >> 5, lane = tid & 31, m = (int)rank*64 + lane;
        wf0 = __ldg(Wf + (size_t)c*HID + m);
        wf1 = __ldg(Wf + (size_t)c*HID + m + 32);
    }
    float bfr = (tid < NCLS) ? __ldg(bfv + tid) : 0.f;

    if (tid < HID) h_s[0][tid] = 0.f;
    if (tid < NCLS) tf_s[tid] = 0.f;
    __syncthreads();
    asm volatile("barrier.cluster.arrive.aligned;" ::: "memory");
    asm volatile("barrier.cluster.wait.aligned;" ::: "memory");

    // DSMEM base addresses for all 4 ranks
    unsigned hloc = smem_u32(&h_s[0][0]);
    unsigned oloc = smem_u32(&op_s[0][0][0]);
    unsigned hb[4], ob[4];
#pragma unroll
    for (int r2 = 0; r2 < 4; r2++) {
        hb[r2] = mapa_rank(hloc, r2);
        ob[r2] = mapa_rank(oloc, r2);
    }

    for (int t = 0; t < TSEQ; t++) {
        const int p = t & 1, pn = p ^ 1;

        // prefetch for tail phase
        float tg = 0.f; int fm = 0;
        if (tid < NCLS) {
            tg = __ldg(targets + ((size_t)b*TSEQ + t)*NCLS + tid);
            fm = __ldg(fmask + t*BATCH + b);
        }
        float gi = 0.f;
        if (tid < 192)
            gi = __ldg(g_gi + ((size_t)t*BATCH + b)*768 + jglob);

        // --- gh = W_hh_slice @ h (register weights, packed f32x2) ---
        unsigned long long a0 = 0ull, a1 = 0ull, a2 = 0ull, a3 = 0ull;
        const ulonglong2* hv =
            reinterpret_cast<const ulonglong2*>(&h_s[p][0]) + kh*32;
#pragma unroll
        for (int kk = 0; kk < 32; kk += 2) {
            ulonglong2 x = hv[kk];
            a0 = fma2(warr[2*kk],   x.x, a0);
            a1 = fma2(warr[2*kk+1], x.y, a1);
            ulonglong2 y = hv[kk+1];
            a2 = fma2(warr[2*kk+2], y.x, a2);
            a3 = fma2(warr[2*kk+3], y.y, a3);
        }
        {
            float2 f0 = ull2f2(a0), f1 = ull2f2(a1), f2 = ull2f2(a2), f3 = ull2f2(a3);
            part_s[jl][kh] = ((f0.x + f0.y) + (f1.x + f1.y))
                           + ((f2.x + f2.y) + (f3.x + f3.y));
        }
        __syncthreads();

        // --- combine halves, add gi + tf contribution ---
        if (tid < 192) {
            float gh = part_s[tid][0] + part_s[tid][1] + bhv;
#pragma unroll
            for (int c = 0; c < NCLS; c++)
                gi = fmaf(tf_s[c], wtf_s[tid][c], gi);
            if (g < 2) pre_s[tid] = gi + gh;
            else { gin_s[u] = gi; ghn_s[u] = gh; }
        }
        __syncthreads();

        // --- gate nonlinearities + h update + DSMEM broadcast ---
        if (tid < 64) {
            float r = 1.f / (1.f + expf(-pre_s[tid]));
            float z = 1.f / (1.f + expf(-pre_s[64 + tid]));
            float n = tanhf(fmaf(r, ghn_s[tid], gin_s[tid]));
            float hold = h_s[p][(int)rank*64 + tid];
            float hn = (1.f - z)*n + z*hold;
            unsigned off = (unsigned)(pn*HID + (int)rank*64 + tid) * 4u;
#pragma unroll
            for (int r2 = 0; r2 < 4; r2++) st_cluster_f32(hb[r2] + off, hn);
        }
        __syncthreads();

        // --- partial output head (own 64 units) + DSMEM broadcast ---
        if (tid < 320) {
            int c = tid >> 5, lane = tid & 31, m = (int)rank*64 + lane;
            float acc = fmaf(h_s[pn][m], wf0, h_s[pn][m + 32] * wf1);
#pragma unroll
            for (int d = 16; d > 0; d >>= 1)
                acc += __shfl_xor_sync(0xffffffffu, acc, d);
            if (lane == 0) {
                unsigned off = (unsigned)(pn*4*NCLS + (int)rank*NCLS + c) * 4u;
#pragma unroll
                for (int r2 = 0; r2 < 4; r2++) st_cluster_f32(ob[r2] + off, acc);
            }
        }
        asm volatile("barrier.cluster.arrive.aligned;" ::: "memory");
        asm volatile("barrier.cluster.wait.aligned;" ::: "memory");

        // --- finalize out, write gmem, update teacher-force state ---
        if (tid < NCLS) {
            float o = ((op_s[pn][0][tid] + op_s[pn][1][tid])
                     + (op_s[pn][2][tid] + op_s[pn][3][tid])) + bfr;
            if (rank == 0)
                outp[((size_t)b*TSEQ + t)*NCLS + tid] = o;
            tf_s[tid] = (fm > 0) ? tg : (o > 0.f ? 1.f : 0.f);
        }
        __syncthreads();
    }
}

// ============================================================
// launch
// ============================================================
extern "C" void kernel_launch(void* const* d_in, const int* in_sizes, int n_in,
                              void* d_out, int out_size)
{
    const float* x       = (const float*)d_in[0];
    const float* targets = (const float*)d_in[1];
    const int*   fmask   = (const int*)  d_in[2];
    const float* W1      = (const float*)d_in[3];
    const float* b1      = (const float*)d_in[4];
    const float* W2      = (const float*)d_in[5];
    const float* b2      = (const float*)d_in[6];
    const float* W3      = (const float*)d_in[7];
    const float* b3      = (const float*)d_in[8];
    const float* W_ih    = (const float*)d_in[9];
    const float* W_hh    = (const float*)d_in[10];
    const float* b_ih    = (const float*)d_in[11];
    const float* b_hh    = (const float*)d_in[12];
    const float* Wf      = (const float*)d_in[13];
    const float* bf      = (const float*)d_in[14];
    float* outp = (float*)d_out;

    float *f1p, *f2p, *featsp;
    cudaGetSymbolAddress((void**)&f1p,    g_f1);
    cudaGetSymbolAddress((void**)&f2p,    g_f2);
    cudaGetSymbolAddress((void**)&featsp, g_feats);

    conv1_kernel<<<dim3(TSEQ/4, BATCH), 512>>>(x, W1, b1);
    conv_cc_kernel<8, 4, false><<<dim3(4, TSEQ/8, BATCH), 256>>>(f1p, W2, b2, f2p);
    conv_cc_kernel<2, 2, true ><<<dim3(4, TSEQ/8, BATCH), 256>>>(f2p, W3, b3, featsp);
    gi_gemm_kernel<<<dim3(12, 512), 256>>>(W_ih, b_ih);
    gru_kernel<<<128, 384>>>(targets, fmask, W_ih, W_hh, b_hh, Wf, bf, outp);
}